// round 2
// baseline (speedup 1.0000x reference)
#include <cuda_runtime.h>
#include <math.h>
#include <stdint.h>

// ---------------------------------------------------------------------------
// CoPE: inv_n = 1/max(||pos_n||,eps)
//       logits = (q @ pos_raw^T) * inv_n / sqrt(D); gates = softmax(logits)
//       out = (gates * inv_n) @ pos_raw
// B=4, T=4096, D=4096, N=16.
// ---------------------------------------------------------------------------

#define DIM        4096
#define DIM4       1024            // float4 per row
#define NPOS       16
#define ROWS_TOT   16384
#define ROWS_BLK   32              // rows per CTA
#define NBLOCKS    (ROWS_TOT / ROWS_BLK)   // 512
#define NTHREADS   512
#define CHUNK_F4   256             // float4 of D per chunk per n-row
#define NCHUNKS    4
#define RED_STRIDE 68

// smem float layout
#define OFF_BUF0    0
#define OFF_BUF1    16384
#define OFF_SCRATCH 32768          // 4*64*68 = 17408
#define OFF_LG      50176          // 32*16
#define OFF_GATES   50688          // 32*16
#define OFF_INV     51200          // 16
#define SMEM_FLOATS 51216
#define SMEM_BYTES  (SMEM_FLOATS * 4)   // 204864

__device__ float g_inv[NPOS];

// ---------------------------------------------------------------------------
__global__ void cope_inv_kernel(const float* __restrict__ pos)
{
    const int n   = blockIdx.x;
    const int tid = threadIdx.x;
    const float* row = pos + n * DIM;

    float s = 0.f;
    #pragma unroll 4
    for (int i = tid; i < DIM; i += 256) {
        float v = row[i];
        s = fmaf(v, v, s);
    }
    #pragma unroll
    for (int o = 16; o > 0; o >>= 1) s += __shfl_down_sync(0xffffffffu, s, o);

    __shared__ float sred[8];
    if ((tid & 31) == 0) sred[tid >> 5] = s;
    __syncthreads();
    if (tid == 0) {
        float t = 0.f;
        #pragma unroll
        for (int w = 0; w < 8; w++) t += sred[w];
        g_inv[n] = 1.0f / fmaxf(sqrtf(t), 1e-12f);
    }
}

// ---------------------------------------------------------------------------
__device__ __forceinline__ void cp_async16(void* s, const void* g)
{
    uint32_t saddr = (uint32_t)__cvta_generic_to_shared(s);
    asm volatile("cp.async.cg.shared.global [%0], [%1], 16;\n"
                 :: "r"(saddr), "l"(g));
}
__device__ __forceinline__ void cp_commit()
{
    asm volatile("cp.async.commit_group;\n" ::);
}

// stage one [16][1024]-float chunk of raw pos into a smem buffer (async)
__device__ __forceinline__ void stage_chunk(float4* buf, const float4* gp4,
                                            int c, int tid)
{
    #pragma unroll
    for (int i = 0; i < 8; i++) {
        int idx = tid + i * NTHREADS;   // 0..4095
        int n   = idx >> 8;
        int d4  = idx & 255;
        cp_async16(buf + n * CHUNK_F4 + d4,
                   gp4 + (size_t)n * DIM4 + (size_t)c * CHUNK_F4 + d4);
    }
}

// ---------------------------------------------------------------------------
__global__ void __launch_bounds__(NTHREADS, 1)
cope_main_kernel(const float* __restrict__ q, const float* __restrict__ pos,
                 float* __restrict__ out)
{
    extern __shared__ float smem[];
    float4* buf0    = (float4*)(smem + OFF_BUF0);
    float4* buf1    = (float4*)(smem + OFF_BUF1);
    float*  scratch = smem + OFF_SCRATCH;
    float*  s_lg    = smem + OFF_LG;
    float*  s_gates = smem + OFF_GATES;
    float*  s_inv   = smem + OFF_INV;

    const int tid   = threadIdx.x;
    const int rgrp  = tid >> 6;             // 0..7 (4 rows each)
    const int dlane = tid & 63;
    const int row0  = blockIdx.x * ROWS_BLK + rgrp * 4;

    const float4* q4   = (const float4*)q;
    const float4* gp4  = (const float4*)pos;
    float4*       out4 = (float4*)out;

    if (tid < NPOS) s_inv[tid] = g_inv[tid];

    // prologue: stage chunks 0,1
    stage_chunk(buf0, gp4, 0, tid); cp_commit();
    stage_chunk(buf1, gp4, 1, tid); cp_commit();

    // ------------------------- pass 1: logits ----------------------------
    float acc[4][16];
    #pragma unroll
    for (int r = 0; r < 4; r++)
        #pragma unroll
        for (int n = 0; n < NPOS; n++) acc[r][n] = 0.f;

    #pragma unroll
    for (int c = 0; c < NCHUNKS; c++) {
        if (c < NCHUNKS - 1) asm volatile("cp.async.wait_group 1;\n" ::);
        else                 asm volatile("cp.async.wait_group 0;\n" ::);
        __syncthreads();

        const float4* sp = (c & 1) ? buf1 : buf0;
        #pragma unroll
        for (int j = 0; j < 4; j++) {
            const int d4 = dlane + j * 64;
            float4 qv[4];
            #pragma unroll
            for (int r = 0; r < 4; r++)
                qv[r] = q4[(size_t)(row0 + r) * DIM4 + (size_t)c * CHUNK_F4 + d4];

            #pragma unroll
            for (int n = 0; n < NPOS; n++) {
                const float4 p = sp[n * CHUNK_F4 + d4];
                #pragma unroll
                for (int r = 0; r < 4; r++) {
                    float a = acc[r][n];
                    a = fmaf(qv[r].x, p.x, a);
                    a = fmaf(qv[r].y, p.y, a);
                    a = fmaf(qv[r].z, p.z, a);
                    a = fmaf(qv[r].w, p.w, a);
                    acc[r][n] = a;
                }
            }
        }
        __syncthreads();
        if (c + 2 < NCHUNKS) {
            stage_chunk((c & 1) ? buf1 : buf0, gp4, c + 2, tid);
            cp_commit();
        }
    }

    // prefetch pass-2 chunks 0,1 (overlaps reduction + softmax)
    stage_chunk(buf0, gp4, 0, tid); cp_commit();
    stage_chunk(buf1, gp4, 1, tid); cp_commit();

    // ---------------- reduce 64 d-lanes -> logits[32][16] ----------------
    // phase A: row groups 0..3
    if (rgrp < 4) {
        float4* b4 = (float4*)(scratch + (size_t)(rgrp * 64 + dlane) * RED_STRIDE);
        #pragma unroll
        for (int r = 0; r < 4; r++)
            #pragma unroll
            for (int g = 0; g < 4; g++)
                b4[r * 4 + g] = make_float4(acc[r][4*g+0], acc[r][4*g+1],
                                            acc[r][4*g+2], acc[r][4*g+3]);
    }
    __syncthreads();
    if (tid < 256) {
        const int r = tid >> 4, n = tid & 15;
        const float* p = scratch + (size_t)((r >> 2) * 64) * RED_STRIDE
                                 + (r & 3) * 16 + n;
        float s = 0.f;
        #pragma unroll 8
        for (int k = 0; k < 64; k++) s += p[(size_t)k * RED_STRIDE];
        s_lg[r * 16 + n] = s * 0.015625f * s_inv[n];
    }
    __syncthreads();
    // phase B: row groups 4..7
    if (rgrp >= 4) {
        float4* b4 = (float4*)(scratch + (size_t)((rgrp - 4) * 64 + dlane) * RED_STRIDE);
        #pragma unroll
        for (int r = 0; r < 4; r++)
            #pragma unroll
            for (int g = 0; g < 4; g++)
                b4[r * 4 + g] = make_float4(acc[r][4*g+0], acc[r][4*g+1],
                                            acc[r][4*g+2], acc[r][4*g+3]);
    }
    __syncthreads();
    if (tid < 256) {
        const int r = tid >> 4, n = tid & 15;
        const float* p = scratch + (size_t)((r >> 2) * 64) * RED_STRIDE
                                 + (r & 3) * 16 + n;
        float s = 0.f;
        #pragma unroll 8
        for (int k = 0; k < 64; k++) s += p[(size_t)k * RED_STRIDE];
        s_lg[(16 + r) * 16 + n] = s * 0.015625f * s_inv[n];
    }
    __syncthreads();

    // ------------------------------ softmax ------------------------------
    if (tid < ROWS_BLK) {
        const int r = tid;
        float m = -1e30f;
        #pragma unroll
        for (int n = 0; n < NPOS; n++) m = fmaxf(m, s_lg[r * 16 + n]);
        float e[NPOS];
        float sum = 0.f;
        #pragma unroll
        for (int n = 0; n < NPOS; n++) {
            e[n] = expf(s_lg[r * 16 + n] - m);
            sum += e[n];
        }
        const float invs = 1.0f / sum;
        #pragma unroll
        for (int n = 0; n < NPOS; n++)
            s_gates[r * 16 + n] = e[n] * invs * s_inv[n];   // fold inv_norm
    }
    __syncthreads();

    // -------------------------- pass 2: output ---------------------------
    float gt[4][16];
    #pragma unroll
    for (int r = 0; r < 4; r++)
        #pragma unroll
        for (int n = 0; n < NPOS; n++)
            gt[r][n] = s_gates[(rgrp * 4 + r) * 16 + n];

    #pragma unroll
    for (int c = 0; c < NCHUNKS; c++) {
        if (c < NCHUNKS - 1) asm volatile("cp.async.wait_group 1;\n" ::);
        else                 asm volatile("cp.async.wait_group 0;\n" ::);
        __syncthreads();

        const float4* sp = (c & 1) ? buf1 : buf0;
        #pragma unroll
        for (int j = 0; j < 4; j++) {
            const int d4 = dlane + j * 64;
            float4 o[4];
            #pragma unroll
            for (int r = 0; r < 4; r++) o[r] = make_float4(0.f, 0.f, 0.f, 0.f);

            #pragma unroll
            for (int n = 0; n < NPOS; n++) {
                const float4 p = sp[n * CHUNK_F4 + d4];
                #pragma unroll
                for (int r = 0; r < 4; r++) {
                    o[r].x = fmaf(gt[r][n], p.x, o[r].x);
                    o[r].y = fmaf(gt[r][n], p.y, o[r].y);
                    o[r].z = fmaf(gt[r][n], p.z, o[r].z);
                    o[r].w = fmaf(gt[r][n], p.w, o[r].w);
                }
            }
            #pragma unroll
            for (int r = 0; r < 4; r++)
                out4[(size_t)(row0 + r) * DIM4 + (size_t)c * CHUNK_F4 + d4] = o[r];
        }
        __syncthreads();
        if (c + 2 < NCHUNKS) {
            stage_chunk((c & 1) ? buf1 : buf0, gp4, c + 2, tid);
            cp_commit();
        }
    }
}

// ---------------------------------------------------------------------------
extern "C" void kernel_launch(void* const* d_in, const int* in_sizes, int n_in,
                              void* d_out, int out_size)
{
    const float* q   = (const float*)d_in[0];
    // d_in[1] = x : unused by the reference computation
    const float* pos = (const float*)d_in[2];
    float* out = (float*)d_out;

    cudaFuncSetAttribute(cope_main_kernel,
                         cudaFuncAttributeMaxDynamicSharedMemorySize, SMEM_BYTES);

    cope_inv_kernel<<<NPOS, 256>>>(pos);
    cope_main_kernel<<<NBLOCKS, NTHREADS, SMEM_BYTES>>>(q, pos, out);
}

// round 3
// speedup vs baseline: 2.1590x; 2.1590x over previous
#include <cuda_runtime.h>
#include <math.h>
#include <stdint.h>

// ---------------------------------------------------------------------------
// CoPE with packed f32x2 FMA:
//   inv_n = 1/max(||pos_n||, eps)
//   logits = (q @ pos^T) * inv_n / sqrt(D); gates = softmax(logits)
//   out = (gates * inv_n) @ pos
// B=4, T=4096, D=4096, N=16.
// ---------------------------------------------------------------------------

typedef unsigned long long ull;

#define DIM        4096
#define DIM4       1024               // float4 per row
#define NPOS       16
#define ROWS_TOT   16384
#define ROWS_BLK   16
#define NBLOCKS    (ROWS_TOT / ROWS_BLK)   // 1024
#define NTHREADS   128
#define CHUNK_F4   128                // float4 of D per n-row per chunk
#define NCHUNKS    8

// smem float layout
#define BUF_FLOATS (NPOS * CHUNK_F4 * 4)   // 8192 floats = 32KB
#define OFF_BUF0   0
#define OFF_BUF1   BUF_FLOATS
#define OFF_SCR    (2 * BUF_FLOATS)        // 16384
#define SCR_STRIDE 68
#define SCR_FLOATS (4 * 32 * SCR_STRIDE)   // 8704
#define OFF_LG     (OFF_SCR + SCR_FLOATS)  // 25088
#define OFF_GATES  (OFF_LG + 256)
#define OFF_INV    (OFF_GATES + 256)
#define SMEM_FLOATS (OFF_INV + 16)
#define SMEM_BYTES (SMEM_FLOATS * 4)       // ~100.3 KB -> 2 CTAs/SM

__device__ float g_inv[NPOS];

// ---------------------------------------------------------------------------
__global__ void cope_inv_kernel(const float* __restrict__ pos)
{
    const int n   = blockIdx.x;
    const int tid = threadIdx.x;
    const float* row = pos + n * DIM;

    float s = 0.f;
    #pragma unroll 4
    for (int i = tid; i < DIM; i += 256) {
        float v = row[i];
        s = fmaf(v, v, s);
    }
    #pragma unroll
    for (int o = 16; o > 0; o >>= 1) s += __shfl_down_sync(0xffffffffu, s, o);

    __shared__ float sred[8];
    if ((tid & 31) == 0) sred[tid >> 5] = s;
    __syncthreads();
    if (tid == 0) {
        float t = 0.f;
        #pragma unroll
        for (int w = 0; w < 8; w++) t += sred[w];
        g_inv[n] = 1.0f / fmaxf(sqrtf(t), 1e-12f);
    }
}

// ---------------------------------------------------------------------------
__device__ __forceinline__ ull ffma2(ull a, ull b, ull c)
{
    ull d;
    asm("fma.rn.f32x2 %0, %1, %2, %3;" : "=l"(d) : "l"(a), "l"(b), "l"(c));
    return d;
}
__device__ __forceinline__ ull pack2(float lo, float hi)
{
    return ((ull)__float_as_uint(hi) << 32) | (ull)__float_as_uint(lo);
}
__device__ __forceinline__ float lo2(ull a) { return __uint_as_float((unsigned)(a & 0xffffffffu)); }
__device__ __forceinline__ float hi2(ull a) { return __uint_as_float((unsigned)(a >> 32)); }

__device__ __forceinline__ void cp_async16(void* s, const void* g)
{
    uint32_t saddr = (uint32_t)__cvta_generic_to_shared(s);
    asm volatile("cp.async.cg.shared.global [%0], [%1], 16;\n"
                 :: "r"(saddr), "l"(g));
}
__device__ __forceinline__ void cp_commit()
{
    asm volatile("cp.async.commit_group;\n" ::);
}
__device__ __forceinline__ void cp_wait1()
{
    asm volatile("cp.async.wait_group 1;\n" ::);
}
__device__ __forceinline__ void cp_wait0()
{
    asm volatile("cp.async.wait_group 0;\n" ::);
}

// stage one [16][512]-float chunk of raw pos (async); 16 float4 per thread
__device__ __forceinline__ void stage_chunk(float4* buf, const float4* gp4,
                                            int c, int tid)
{
    #pragma unroll
    for (int i = 0; i < 16; i++) {
        int idx = tid + i * NTHREADS;        // 0..2047
        int n   = idx >> 7;                  // /128
        int d4  = idx & 127;
        cp_async16(buf + n * CHUNK_F4 + d4,
                   gp4 + (size_t)n * DIM4 + (size_t)c * CHUNK_F4 + d4);
    }
}

// ---------------------------------------------------------------------------
__global__ void __launch_bounds__(NTHREADS, 2)
cope_main_kernel(const float* __restrict__ q, const float* __restrict__ pos,
                 float* __restrict__ out)
{
    extern __shared__ float smem[];
    float4* buf0    = (float4*)(smem + OFF_BUF0);
    float4* buf1    = (float4*)(smem + OFF_BUF1);
    float*  scr     = smem + OFF_SCR;
    float*  s_lg    = smem + OFF_LG;
    float*  s_gates = smem + OFF_GATES;
    float*  s_inv   = smem + OFF_INV;

    const int tid   = threadIdx.x;
    const int rgrp  = tid >> 5;              // 0..3, == warp id (4 rows each)
    const int dlane = tid & 31;
    const int row0  = blockIdx.x * ROWS_BLK + rgrp * 4;

    const ulonglong2* qq  = (const ulonglong2*)q;
    const float4*     gp4 = (const float4*)pos;
    ulonglong2*       oo  = (ulonglong2*)out;

    if (tid < NPOS) s_inv[tid] = g_inv[tid];

    // prologue: stage chunks 0,1
    stage_chunk(buf0, gp4, 0, tid); cp_commit();
    stage_chunk(buf1, gp4, 1, tid); cp_commit();

    // ------------------------- pass 1: logits ----------------------------
    ull acc[4][16];
    #pragma unroll
    for (int r = 0; r < 4; r++)
        #pragma unroll
        for (int n = 0; n < NPOS; n++) acc[r][n] = 0ull;

    for (int c = 0; c < NCHUNKS; c++) {
        if (c < NCHUNKS - 1) cp_wait1(); else cp_wait0();
        __syncthreads();

        const ulonglong2* sp =
            (const ulonglong2*)((c & 1) ? buf1 : buf0);

        #pragma unroll
        for (int j = 0; j < 4; j++) {
            const int d4 = dlane + j * 32;
            ulonglong2 qv[4];
            #pragma unroll
            for (int r = 0; r < 4; r++)
                qv[r] = qq[(size_t)(row0 + r) * DIM4 + (size_t)c * CHUNK_F4 + d4];

            #pragma unroll
            for (int n = 0; n < NPOS; n++) {
                const ulonglong2 p = sp[n * CHUNK_F4 + d4];
                #pragma unroll
                for (int r = 0; r < 4; r++) {
                    ull a = acc[r][n];
                    a = ffma2(qv[r].x, p.x, a);
                    a = ffma2(qv[r].y, p.y, a);
                    acc[r][n] = a;
                }
            }
        }
        __syncthreads();
        if (c + 2 < NCHUNKS) {
            stage_chunk((c & 1) ? buf1 : buf0, gp4, c + 2, tid);
            cp_commit();
        }
    }
    // buffers now hold: buf0 = chunk 6, buf1 = chunk 7

    // ---------------- fold f32x2 + reduce 32 dlanes -> logits -------------
    {
        float s[4][16];
        #pragma unroll
        for (int r = 0; r < 4; r++)
            #pragma unroll
            for (int n = 0; n < NPOS; n++)
                s[r][n] = lo2(acc[r][n]) + hi2(acc[r][n]);

        float4* w = (float4*)(scr + (size_t)(rgrp * 32 + dlane) * SCR_STRIDE);
        #pragma unroll
        for (int r = 0; r < 4; r++)
            #pragma unroll
            for (int g = 0; g < 4; g++)
                w[r * 4 + g] = make_float4(s[r][4*g+0], s[r][4*g+1],
                                           s[r][4*g+2], s[r][4*g+3]);
    }
    __syncthreads();
    #pragma unroll
    for (int h = 0; h < 2; h++) {
        const int rn = tid + h * NTHREADS;    // 0..255
        const int rr = rn >> 4, n = rn & 15;
        const float* p = scr + (size_t)((rr >> 2) * 32) * SCR_STRIDE
                             + (rr & 3) * 16 + n;
        float ssum = 0.f;
        #pragma unroll 8
        for (int k = 0; k < 32; k++) ssum += p[(size_t)k * SCR_STRIDE];
        s_lg[rn] = ssum * 0.015625f * s_inv[n];   // * 1/sqrt(4096) * inv_norm
    }
    __syncthreads();

    // ------------------------------ softmax ------------------------------
    if (tid < ROWS_BLK) {
        const int r = tid;
        float m = -1e30f;
        #pragma unroll
        for (int n = 0; n < NPOS; n++) m = fmaxf(m, s_lg[r * 16 + n]);
        float e[NPOS];
        float sum = 0.f;
        #pragma unroll
        for (int n = 0; n < NPOS; n++) {
            e[n] = expf(s_lg[r * 16 + n] - m);
            sum += e[n];
        }
        const float invs = 1.0f / sum;
        #pragma unroll
        for (int n = 0; n < NPOS; n++)
            s_gates[r * 16 + n] = e[n] * invs * s_inv[n];  // fold inv_norm
    }
    __syncthreads();

    // -------------------------- pass 2: output ---------------------------
    // reverse chunk order: chunks 7 (buf1) and 6 (buf0) are already resident
    ull gt[4][16];
    #pragma unroll
    for (int r = 0; r < 4; r++)
        #pragma unroll
        for (int n = 0; n < NPOS; n++) {
            float g = s_gates[(rgrp * 4 + r) * 16 + n];
            gt[r][n] = pack2(g, g);
        }

    for (int cc = 0; cc < NCHUNKS; cc++) {
        const int c = NCHUNKS - 1 - cc;
        if (c <= NCHUNKS - 3) {                 // staged chunks need a wait
            if (c > 0) cp_wait1(); else cp_wait0();
        }
        __syncthreads();

        const ulonglong2* sp =
            (const ulonglong2*)((c & 1) ? buf1 : buf0);

        #pragma unroll
        for (int j = 0; j < 4; j++) {
            const int d4 = dlane + j * 32;
            ulonglong2 o[4];
            #pragma unroll
            for (int r = 0; r < 4; r++) { o[r].x = 0ull; o[r].y = 0ull; }

            #pragma unroll
            for (int n = 0; n < NPOS; n++) {
                const ulonglong2 p = sp[n * CHUNK_F4 + d4];
                #pragma unroll
                for (int r = 0; r < 4; r++) {
                    o[r].x = ffma2(gt[r][n], p.x, o[r].x);
                    o[r].y = ffma2(gt[r][n], p.y, o[r].y);
                }
            }
            #pragma unroll
            for (int r = 0; r < 4; r++)
                oo[(size_t)(row0 + r) * DIM4 + (size_t)c * CHUNK_F4 + d4] = o[r];
        }
        __syncthreads();
        if (c >= 2) {
            stage_chunk((c & 1) ? buf1 : buf0, gp4, c - 2, tid);
            cp_commit();
        }
    }
}

// ---------------------------------------------------------------------------
extern "C" void kernel_launch(void* const* d_in, const int* in_sizes, int n_in,
                              void* d_out, int out_size)
{
    const float* q   = (const float*)d_in[0];
    // d_in[1] = x : unused by the reference computation
    const float* pos = (const float*)d_in[2];
    float* out = (float*)d_out;

    cudaFuncSetAttribute(cope_main_kernel,
                         cudaFuncAttributeMaxDynamicSharedMemorySize, SMEM_BYTES);

    cope_inv_kernel<<<NPOS, 256>>>(pos);
    cope_main_kernel<<<NBLOCKS, NTHREADS, SMEM_BYTES>>>(q, pos, out);
}